// round 2
// baseline (speedup 1.0000x reference)
#include <cuda_runtime.h>

#define BATCH 2048
#define HID   1024
#define FFN   4096
#define NE    8

// ---- device scratch (no allocations allowed) ----
__device__ int   g_cnt[NE];
__device__ int   g_tok[NE][BATCH];
__device__ float g_wgt[NE][BATCH];
__device__ int   g_flags[4];   // [0]: smallA is indices, [1]: indices are int64, [2]: bigA is w1
__device__ float g_H[(size_t)NE * BATCH * FFN];   // 256 MiB fp32 scratch (bss)

// ---------------------------------------------------------------------------
// classify a "small" buffer (4096 logical elements):
// returns 1 = int64 indices, 2 = int32 indices, 0 = float routing weights
__device__ int classify_small(const unsigned* w) {
    bool i64 = true, i32 = true;
    for (int j = 0; j < 32; j++) {
        unsigned v = w[j];
        if (j & 1) { if (v != 0u) i64 = false; }
        else       { if (v >= 8u) i64 = false; }
        if (v >= 8u) i32 = false;
    }
    if (i64) return 1;
    if (i32) return 2;
    return 0;
}

__global__ void k_detect(const unsigned* smallA, const unsigned* smallB,
                         const float* bigA, const float* bigB) {
    __shared__ float sA[256], sB[256];
    int t = threadIdx.x;
    float a = 0.f, b = 0.f;
    for (int i = t; i < 4096; i += 256) {
        a += fabsf(bigA[i]);
        b += fabsf(bigB[i]);
    }
    sA[t] = a; sB[t] = b;
    __syncthreads();
    for (int s = 128; s > 0; s >>= 1) {
        if (t < s) { sA[t] += sA[t + s]; sB[t] += sB[t + s]; }
        __syncthreads();
    }
    if (t < NE) g_cnt[t] = 0;
    if (t == 0) {
        g_flags[2] = (sA[0] > sB[0]) ? 1 : 0;   // larger scale (H^-0.5) => w1
        int tA = classify_small(smallA);
        if (tA != 0) { g_flags[0] = 1; g_flags[1] = (tA == 1); }
        else {
            int tB = classify_small(smallB);
            g_flags[0] = 0; g_flags[1] = (tB == 1);
        }
    }
}

// ---------------------------------------------------------------------------
// one thread per token: dedupe top-2 and append to per-expert lists
__global__ void k_route(const void* smallA, const void* smallB) {
    int b = blockIdx.x * blockDim.x + threadIdx.x;
    if (b >= BATCH) return;
    const void*  idxp = g_flags[0] ? smallA : smallB;
    const float* rw   = (const float*)(g_flags[0] ? smallB : smallA);
    int e0, e1;
    if (g_flags[1]) {
        e0 = (int)((const long long*)idxp)[b * 2 + 0];
        e1 = (int)((const long long*)idxp)[b * 2 + 1];
    } else {
        e0 = ((const int*)idxp)[b * 2 + 0];
        e1 = ((const int*)idxp)[b * 2 + 1];
    }
    float w0 = rw[b * 2 + 0];
    float w1 = rw[b * 2 + 1];
    if (e0 == e1) {
        int p = atomicAdd(&g_cnt[e0], 1);
        g_tok[e0][p] = b;
        g_wgt[e0][p] = w0 + w1;
    } else {
        int p = atomicAdd(&g_cnt[e0], 1);
        g_tok[e0][p] = b;
        g_wgt[e0][p] = w0;
        p = atomicAdd(&g_cnt[e1], 1);
        g_tok[e1][p] = b;
        g_wgt[e1][p] = w1;
    }
}

// ---------------------------------------------------------------------------
// GEMM1: H[e, pos, f] = silu( X[tok] . W1[e][:, f] )
// grid: (FFN/64, BATCH/64, NE), block: 256, 64x64 tile, BK=16, 4x4 microtile
__global__ __launch_bounds__(256)
void k_gemm1(const float* __restrict__ X,
             const float* __restrict__ bigA, const float* __restrict__ bigB) {
    const float* W1 = g_flags[2] ? bigA : bigB;
    int e    = blockIdx.z;
    int cnt  = g_cnt[e];
    int row0 = blockIdx.y * 64;
    if (row0 >= cnt) return;
    int col0 = blockIdx.x * 64;

    __shared__ __align__(16) float As[16][68];   // [k][m]
    __shared__ __align__(16) float Bs[16][64];   // [k][n]
    __shared__ int stok[64];

    int tid = threadIdx.x;
    if (tid < 64) {
        int r = row0 + tid;
        stok[tid] = (r < cnt) ? g_tok[e][r] : 0;
    }
    __syncthreads();

    const float* W = W1 + (size_t)e * HID * FFN + col0;

    int ar  = tid >> 2;           // A-load row 0..63
    int ac4 = (tid & 3) * 4;      // A-load k offset
    int bkr = tid >> 4;           // B-load k row 0..15
    int bc4 = (tid & 15) * 4;     // B-load col offset
    int atok = stok[ar];
    const float* Arow = X + (size_t)atok * HID;

    int ty = tid >> 4, tx = tid & 15;
    float acc[4][4] = {};

    for (int k0 = 0; k0 < HID; k0 += 16) {
        float4 av = *(const float4*)(Arow + k0 + ac4);
        As[ac4 + 0][ar] = av.x;
        As[ac4 + 1][ar] = av.y;
        As[ac4 + 2][ar] = av.z;
        As[ac4 + 3][ar] = av.w;
        *(float4*)&Bs[bkr][bc4] =
            *(const float4*)(W + (size_t)(k0 + bkr) * FFN + bc4);
        __syncthreads();
#pragma unroll
        for (int k = 0; k < 16; k++) {
            float4 a = *(const float4*)&As[k][ty * 4];
            float4 b = *(const float4*)&Bs[k][tx * 4];
            acc[0][0] += a.x * b.x; acc[0][1] += a.x * b.y;
            acc[0][2] += a.x * b.z; acc[0][3] += a.x * b.w;
            acc[1][0] += a.y * b.x; acc[1][1] += a.y * b.y;
            acc[1][2] += a.y * b.z; acc[1][3] += a.y * b.w;
            acc[2][0] += a.z * b.x; acc[2][1] += a.z * b.y;
            acc[2][2] += a.z * b.z; acc[2][3] += a.z * b.w;
            acc[3][0] += a.w * b.x; acc[3][1] += a.w * b.y;
            acc[3][2] += a.w * b.z; acc[3][3] += a.w * b.w;
        }
        __syncthreads();
    }

#pragma unroll
    for (int i = 0; i < 4; i++) {
        int r = row0 + ty * 4 + i;
        if (r < cnt) {
            float* Hrow = g_H + ((size_t)e * BATCH + r) * FFN + col0 + tx * 4;
#pragma unroll
            for (int j = 0; j < 4; j++) {
                float v = acc[i][j];
                Hrow[j] = v / (1.0f + __expf(-v));   // silu
            }
        }
    }
}

// ---------------------------------------------------------------------------
// GEMM2: out[tok] += wgt * ( H[e, pos, :] . W2[e][:, h] )
// grid: (HID/64, BATCH/64, NE), block: 256
__global__ __launch_bounds__(256)
void k_gemm2(const float* __restrict__ bigA, const float* __restrict__ bigB,
             float* __restrict__ out) {
    const float* W2 = g_flags[2] ? bigB : bigA;
    int e    = blockIdx.z;
    int cnt  = g_cnt[e];
    int row0 = blockIdx.y * 64;
    if (row0 >= cnt) return;
    int col0 = blockIdx.x * 64;

    __shared__ __align__(16) float As[16][68];
    __shared__ __align__(16) float Bs[16][64];
    __shared__ int   stok[64];
    __shared__ float swt[64];

    int tid = threadIdx.x;
    if (tid < 64) {
        int r = row0 + tid;
        stok[tid] = (r < cnt) ? g_tok[e][r] : 0;
        swt[tid]  = (r < cnt) ? g_wgt[e][r] : 0.0f;
    }
    __syncthreads();

    const float* Hbase = g_H + ((size_t)e * BATCH + row0) * FFN;
    const float* W     = W2 + (size_t)e * FFN * HID + col0;

    int ar  = tid >> 2;
    int ac4 = (tid & 3) * 4;
    int bkr = tid >> 4;
    int bc4 = (tid & 15) * 4;
    const float* Arow = Hbase + (size_t)ar * FFN;

    int ty = tid >> 4, tx = tid & 15;
    float acc[4][4] = {};

    for (int k0 = 0; k0 < FFN; k0 += 16) {
        float4 av = *(const float4*)(Arow + k0 + ac4);
        As[ac4 + 0][ar] = av.x;
        As[ac4 + 1][ar] = av.y;
        As[ac4 + 2][ar] = av.z;
        As[ac4 + 3][ar] = av.w;
        *(float4*)&Bs[bkr][bc4] =
            *(const float4*)(W + (size_t)(k0 + bkr) * HID + bc4);
        __syncthreads();
#pragma unroll
        for (int k = 0; k < 16; k++) {
            float4 a = *(const float4*)&As[k][ty * 4];
            float4 b = *(const float4*)&Bs[k][tx * 4];
            acc[0][0] += a.x * b.x; acc[0][1] += a.x * b.y;
            acc[0][2] += a.x * b.z; acc[0][3] += a.x * b.w;
            acc[1][0] += a.y * b.x; acc[1][1] += a.y * b.y;
            acc[1][2] += a.y * b.z; acc[1][3] += a.y * b.w;
            acc[2][0] += a.z * b.x; acc[2][1] += a.z * b.y;
            acc[2][2] += a.z * b.z; acc[2][3] += a.z * b.w;
            acc[3][0] += a.w * b.x; acc[3][1] += a.w * b.y;
            acc[3][2] += a.w * b.z; acc[3][3] += a.w * b.w;
        }
        __syncthreads();
    }

#pragma unroll
    for (int i = 0; i < 4; i++) {
        int r = row0 + ty * 4 + i;
        if (r < cnt) {
            int   t = stok[ty * 4 + i];
            float w = swt[ty * 4 + i];
            float* orow = out + (size_t)t * HID + col0 + tx * 4;
#pragma unroll
            for (int j = 0; j < 4; j++)
                atomicAdd(&orow[j], w * acc[i][j]);
        }
    }
}

// ---------------------------------------------------------------------------
extern "C" void kernel_launch(void* const* d_in, const int* in_sizes, int n_in,
                              void* d_out, int out_size) {
    // Bind inputs BY SIZE (metadata order unknown/untrusted):
    //   2,097,152 -> hidden_states; 4096 x2 -> {routing_weights, expert_indices};
    //   33,554,432 x2 -> {w1, w2}. Content-classification happens on device.
    const float* X = nullptr;
    const void*  smallbuf[2] = {nullptr, nullptr};
    const float* bigbuf[2]   = {nullptr, nullptr};
    int ns = 0, nb = 0;
    for (int i = 0; i < n_in; i++) {
        long long s = in_sizes[i];
        if (s == (long long)BATCH * HID)            X = (const float*)d_in[i];
        else if (s == (long long)BATCH * 2)         { if (ns < 2) smallbuf[ns++] = d_in[i]; }
        else if (s == (long long)NE * HID * FFN)    { if (nb < 2) bigbuf[nb++] = (const float*)d_in[i]; }
    }
    float* out = (float*)d_out;

    cudaMemsetAsync(out, 0, (size_t)out_size * sizeof(float));
    k_detect<<<1, 256>>>((const unsigned*)smallbuf[0], (const unsigned*)smallbuf[1],
                         bigbuf[0], bigbuf[1]);
    k_route<<<(BATCH + 255) / 256, 256>>>(smallbuf[0], smallbuf[1]);
    k_gemm1<<<dim3(FFN / 64, BATCH / 64, NE), 256>>>(X, bigbuf[0], bigbuf[1]);
    k_gemm2<<<dim3(HID / 64, BATCH / 64, NE), 256>>>(bigbuf[0], bigbuf[1], out);
}

// round 3
// speedup vs baseline: 1.1219x; 1.1219x over previous
#include <cuda_runtime.h>

#define BATCH 2048
#define HID   1024
#define FFN   4096
#define NE    8

// ---- device scratch (no allocations allowed) ----
__device__ int   g_cnt[NE];
__device__ int   g_tok[NE][BATCH];
__device__ float g_wgt[NE][BATCH];
__device__ int   g_flags[4];   // [0]: smallA is indices, [1]: int64, [2]: bigA is w1
__device__ float g_H[(size_t)NE * BATCH * FFN];   // 256 MiB fp32 scratch (bss)

// ---- packed f32x2 helpers (Blackwell FFMA2 path) ----
__device__ __forceinline__ unsigned long long dup2(float x) {
    unsigned long long r;
    asm("mov.b64 %0, {%1, %1};" : "=l"(r) : "f"(x));
    return r;
}
__device__ __forceinline__ void ffma2(unsigned long long& acc,
                                      unsigned long long a, unsigned long long b) {
    asm("fma.rn.f32x2 %0, %1, %2, %0;" : "+l"(acc) : "l"(a), "l"(b));
}
__device__ __forceinline__ float2 unp2(unsigned long long v) {
    float2 f;
    asm("mov.b64 {%0, %1}, %2;" : "=f"(f.x), "=f"(f.y) : "l"(v));
    return f;
}
union F4U { float4 v; unsigned long long u[2]; float f[4]; };

// ---------------------------------------------------------------------------
// classify small buffer: 1 = int64 indices, 2 = int32 indices, 0 = floats
__device__ int classify_small(const unsigned* w) {
    bool i64 = true, i32 = true;
    for (int j = 0; j < 32; j++) {
        unsigned v = w[j];
        if (j & 1) { if (v != 0u) i64 = false; }
        else       { if (v >= 8u) i64 = false; }
        if (v >= 8u) i32 = false;
    }
    if (i64) return 1;
    if (i32) return 2;
    return 0;
}

__global__ void k_detect(const unsigned* smallA, const unsigned* smallB,
                         const float* bigA, const float* bigB) {
    __shared__ float sA[256], sB[256];
    int t = threadIdx.x;
    float a = 0.f, b = 0.f;
    for (int i = t; i < 4096; i += 256) { a += fabsf(bigA[i]); b += fabsf(bigB[i]); }
    sA[t] = a; sB[t] = b;
    __syncthreads();
    for (int s = 128; s > 0; s >>= 1) {
        if (t < s) { sA[t] += sA[t + s]; sB[t] += sB[t + s]; }
        __syncthreads();
    }
    if (t < NE) g_cnt[t] = 0;
    if (t == 0) {
        g_flags[2] = (sA[0] > sB[0]) ? 1 : 0;   // larger scale (H^-0.5) => w1
        int tA = classify_small(smallA);
        if (tA != 0) { g_flags[0] = 1; g_flags[1] = (tA == 1); }
        else {
            int tB = classify_small(smallB);
            g_flags[0] = 0; g_flags[1] = (tB == 1);
        }
    }
}

// ---------------------------------------------------------------------------
__global__ void k_route(const void* smallA, const void* smallB) {
    int b = blockIdx.x * blockDim.x + threadIdx.x;
    if (b >= BATCH) return;
    const void*  idxp = g_flags[0] ? smallA : smallB;
    const float* rw   = (const float*)(g_flags[0] ? smallB : smallA);
    int e0, e1;
    if (g_flags[1]) {
        e0 = (int)((const long long*)idxp)[b * 2 + 0];
        e1 = (int)((const long long*)idxp)[b * 2 + 1];
    } else {
        e0 = ((const int*)idxp)[b * 2 + 0];
        e1 = ((const int*)idxp)[b * 2 + 1];
    }
    float w0 = rw[b * 2 + 0];
    float w1 = rw[b * 2 + 1];
    if (e0 == e1) {
        int p = atomicAdd(&g_cnt[e0], 1);
        g_tok[e0][p] = b; g_wgt[e0][p] = w0 + w1;
    } else {
        int p = atomicAdd(&g_cnt[e0], 1);
        g_tok[e0][p] = b; g_wgt[e0][p] = w0;
        p = atomicAdd(&g_cnt[e1], 1);
        g_tok[e1][p] = b; g_wgt[e1][p] = w1;
    }
}

// ---------------------------------------------------------------------------
// 128x128 tile, BK=16, 256 threads, 8x8 microtile on packed f32x2 FFMA.
// GEMM1: H[e,pos,f] = silu(X[tok] . W1[e][:,f]),  grid (FFN/128, 16, 8)
__global__ __launch_bounds__(256)
void k_gemm1(const float* __restrict__ X,
             const float* __restrict__ bigA, const float* __restrict__ bigB) {
    const float* W1 = g_flags[2] ? bigA : bigB;
    int e    = blockIdx.z;
    int cnt  = g_cnt[e];
    int row0 = blockIdx.y * 128;
    if (row0 >= cnt) return;
    int col0 = blockIdx.x * 128;

    __shared__ __align__(16) float As[16][132];   // [k][m]
    __shared__ __align__(16) float Bs[16][132];   // [k][n]
    __shared__ int stok[128];

    int tid = threadIdx.x;
    if (tid < 128) {
        int r = row0 + tid;
        stok[tid] = (r < cnt) ? g_tok[e][r] : 0;
    }

    const float* W = W1 + (size_t)e * HID * FFN + col0;

    int ar  = tid >> 1;           // A row 0..127
    int ak8 = (tid & 1) * 8;      // A k-offset 0 or 8
    int bkr = tid >> 4;           // B k-row 0..15
    int bc8 = (tid & 15) * 8;     // B col offset

    int ty = tid >> 4, tx = tid & 15;   // 16x16 thread grid
    unsigned long long acc[8][4] = {};

    __syncthreads();              // stok visible
    const float* Arow = X + (size_t)stok[ar] * HID + ak8;
    const float* Brow = W + (size_t)bkr * FFN + bc8;

    float4 a0 = *(const float4*)(Arow);
    float4 a1 = *(const float4*)(Arow + 4);
    float4 b0 = *(const float4*)(Brow);
    float4 b1 = *(const float4*)(Brow + 4);

    for (int k0 = 0; k0 < HID; k0 += 16) {
        // stage regs -> smem
        As[ak8 + 0][ar] = a0.x; As[ak8 + 1][ar] = a0.y;
        As[ak8 + 2][ar] = a0.z; As[ak8 + 3][ar] = a0.w;
        As[ak8 + 4][ar] = a1.x; As[ak8 + 5][ar] = a1.y;
        As[ak8 + 6][ar] = a1.z; As[ak8 + 7][ar] = a1.w;
        *(float4*)&Bs[bkr][bc8]     = b0;
        *(float4*)&Bs[bkr][bc8 + 4] = b1;
        __syncthreads();
        if (k0 + 16 < HID) {
            a0 = *(const float4*)(Arow + k0 + 16);
            a1 = *(const float4*)(Arow + k0 + 20);
            b0 = *(const float4*)(Brow + (size_t)(k0 + 16) * FFN);
            b1 = *(const float4*)(Brow + (size_t)(k0 + 16) * FFN + 4);
        }
#pragma unroll
        for (int k = 0; k < 16; k++) {
            F4U av0, av1, bv0, bv1;
            av0.v = *(const float4*)&As[k][ty * 8];
            av1.v = *(const float4*)&As[k][ty * 8 + 4];
            bv0.v = *(const float4*)&Bs[k][tx * 8];
            bv1.v = *(const float4*)&Bs[k][tx * 8 + 4];
            unsigned long long bp0 = bv0.u[0], bp1 = bv0.u[1];
            unsigned long long bp2 = bv1.u[0], bp3 = bv1.u[1];
#pragma unroll
            for (int i = 0; i < 8; i++) {
                unsigned long long ai = dup2(i < 4 ? av0.f[i] : av1.f[i - 4]);
                ffma2(acc[i][0], ai, bp0);
                ffma2(acc[i][1], ai, bp1);
                ffma2(acc[i][2], ai, bp2);
                ffma2(acc[i][3], ai, bp3);
            }
        }
        __syncthreads();
    }

#pragma unroll
    for (int i = 0; i < 8; i++) {
        int r = row0 + ty * 8 + i;
        if (r < cnt) {
            float* Hrow = g_H + ((size_t)e * BATCH + r) * FFN + col0 + tx * 8;
#pragma unroll
            for (int j = 0; j < 4; j++) {
                float2 p = unp2(acc[i][j]);
                Hrow[j * 2 + 0] = p.x / (1.0f + __expf(-p.x));
                Hrow[j * 2 + 1] = p.y / (1.0f + __expf(-p.y));
            }
        }
    }
}

// ---------------------------------------------------------------------------
// GEMM2: out[tok] += wgt * (H[e,pos,:] . W2[e][:,h]),  grid (HID/128, 16, 8)
__global__ __launch_bounds__(256)
void k_gemm2(const float* __restrict__ bigA, const float* __restrict__ bigB,
             float* __restrict__ out) {
    const float* W2 = g_flags[2] ? bigB : bigA;
    int e    = blockIdx.z;
    int cnt  = g_cnt[e];
    int row0 = blockIdx.y * 128;
    if (row0 >= cnt) return;
    int col0 = blockIdx.x * 128;

    __shared__ __align__(16) float As[16][132];
    __shared__ __align__(16) float Bs[16][132];
    __shared__ int   stok[128];
    __shared__ float swt[128];

    int tid = threadIdx.x;
    if (tid < 128) {
        int r = row0 + tid;
        stok[tid] = (r < cnt) ? g_tok[e][r] : 0;
        swt[tid]  = (r < cnt) ? g_wgt[e][r] : 0.0f;
    }

    const float* Hbase = g_H + ((size_t)e * BATCH + row0) * FFN;
    const float* W     = W2 + (size_t)e * FFN * HID + col0;

    int ar  = tid >> 1;
    int ak8 = (tid & 1) * 8;
    int bkr = tid >> 4;
    int bc8 = (tid & 15) * 8;

    int ty = tid >> 4, tx = tid & 15;
    unsigned long long acc[8][4] = {};

    __syncthreads();
    const float* Arow = Hbase + (size_t)ar * FFN + ak8;
    const float* Brow = W + (size_t)bkr * HID + bc8;

    float4 a0 = *(const float4*)(Arow);
    float4 a1 = *(const float4*)(Arow + 4);
    float4 b0 = *(const float4*)(Brow);
    float4 b1 = *(const float4*)(Brow + 4);

    for (int k0 = 0; k0 < FFN; k0 += 16) {
        As[ak8 + 0][ar] = a0.x; As[ak8 + 1][ar] = a0.y;
        As[ak8 + 2][ar] = a0.z; As[ak8 + 3][ar] = a0.w;
        As[ak8 + 4][ar] = a1.x; As[ak8 + 5][ar] = a1.y;
        As[ak8 + 6][ar] = a1.z; As[ak8 + 7][ar] = a1.w;
        *(float4*)&Bs[bkr][bc8]     = b0;
        *(float4*)&Bs[bkr][bc8 + 4] = b1;
        __syncthreads();
        if (k0 + 16 < FFN) {
            a0 = *(const float4*)(Arow + k0 + 16);
            a1 = *(const float4*)(Arow + k0 + 20);
            b0 = *(const float4*)(Brow + (size_t)(k0 + 16) * HID);
            b1 = *(const float4*)(Brow + (size_t)(k0 + 16) * HID + 4);
        }
#pragma unroll
        for (int k = 0; k < 16; k++) {
            F4U av0, av1, bv0, bv1;
            av0.v = *(const float4*)&As[k][ty * 8];
            av1.v = *(const float4*)&As[k][ty * 8 + 4];
            bv0.v = *(const float4*)&Bs[k][tx * 8];
            bv1.v = *(const float4*)&Bs[k][tx * 8 + 4];
            unsigned long long bp0 = bv0.u[0], bp1 = bv0.u[1];
            unsigned long long bp2 = bv1.u[0], bp3 = bv1.u[1];
#pragma unroll
            for (int i = 0; i < 8; i++) {
                unsigned long long ai = dup2(i < 4 ? av0.f[i] : av1.f[i - 4]);
                ffma2(acc[i][0], ai, bp0);
                ffma2(acc[i][1], ai, bp1);
                ffma2(acc[i][2], ai, bp2);
                ffma2(acc[i][3], ai, bp3);
            }
        }
        __syncthreads();
    }

#pragma unroll
    for (int i = 0; i < 8; i++) {
        int r = row0 + ty * 8 + i;
        if (r < cnt) {
            int   t = stok[ty * 8 + i];
            float w = swt[ty * 8 + i];
            float* orow = out + (size_t)t * HID + col0 + tx * 8;
#pragma unroll
            for (int j = 0; j < 4; j++) {
                float2 p = unp2(acc[i][j]);
                atomicAdd(&orow[j * 2 + 0], w * p.x);
                atomicAdd(&orow[j * 2 + 1], w * p.y);
            }
        }
    }
}

// ---------------------------------------------------------------------------
extern "C" void kernel_launch(void* const* d_in, const int* in_sizes, int n_in,
                              void* d_out, int out_size) {
    const float* X = nullptr;
    const void*  smallbuf[2] = {nullptr, nullptr};
    const float* bigbuf[2]   = {nullptr, nullptr};
    int ns = 0, nb = 0;
    for (int i = 0; i < n_in; i++) {
        long long s = in_sizes[i];
        if (s == (long long)BATCH * HID)            X = (const float*)d_in[i];
        else if (s == (long long)BATCH * 2)         { if (ns < 2) smallbuf[ns++] = d_in[i]; }
        else if (s == (long long)NE * HID * FFN)    { if (nb < 2) bigbuf[nb++] = (const float*)d_in[i]; }
    }
    float* out = (float*)d_out;

    cudaMemsetAsync(out, 0, (size_t)out_size * sizeof(float));
    k_detect<<<1, 256>>>((const unsigned*)smallbuf[0], (const unsigned*)smallbuf[1],
                         bigbuf[0], bigbuf[1]);
    k_route<<<(BATCH + 255) / 256, 256>>>(smallbuf[0], smallbuf[1]);
    k_gemm1<<<dim3(FFN / 128, BATCH / 128, NE), 256>>>(X, bigbuf[0], bigbuf[1]);
    k_gemm2<<<dim3(HID / 128, BATCH / 128, NE), 256>>>(bigbuf[0], bigbuf[1], out);
}

// round 5
// speedup vs baseline: 3.1392x; 2.7980x over previous
#include <cuda_runtime.h>
#include <cuda_fp16.h>
#include <cstdint>

#define BATCH 2048
#define HID   1024
#define FFN   4096
#define NE    8

// ---- device scratch ----
__device__ int    g_cnt[NE];
__device__ int    g_tok[NE][BATCH];
__device__ float  g_wgt[NE][BATCH];
__device__ int    g_flags[4];
__device__ __half g_H[(size_t)NE * BATCH * FFN];   // 128 MiB fp16 intermediate

// ---- helpers ----
static __device__ __forceinline__ uint32_t smem_u32(const void* p) {
    uint32_t a;
    asm("{ .reg .u64 t; cvta.to.shared.u64 t, %1; cvt.u32.u64 %0, t; }" : "=r"(a) : "l"(p));
    return a;
}
static __device__ __forceinline__ uint32_t h2(float a, float b) {
    __half2 h = __floats2half2_rn(a, b);
    return *(uint32_t*)&h;
}
static __device__ __forceinline__ void st4(uint32_t addr, uint32_t x, uint32_t y,
                                           uint32_t z, uint32_t w) {
    asm volatile("st.shared.v4.b32 [%0], {%1,%2,%3,%4};"
                 :: "r"(addr), "r"(x), "r"(y), "r"(z), "r"(w) : "memory");
}
static __device__ __forceinline__ void ldsm_x4(unsigned* r, uint32_t addr) {
    asm volatile("ldmatrix.sync.aligned.m8n8.x4.shared.b16 {%0,%1,%2,%3}, [%4];"
                 : "=r"(r[0]), "=r"(r[1]), "=r"(r[2]), "=r"(r[3]) : "r"(addr));
}
static __device__ __forceinline__ void ldsm_x4_t(unsigned* r, uint32_t addr) {
    asm volatile("ldmatrix.sync.aligned.m8n8.x4.trans.shared.b16 {%0,%1,%2,%3}, [%4];"
                 : "=r"(r[0]), "=r"(r[1]), "=r"(r[2]), "=r"(r[3]) : "r"(addr));
}
static __device__ __forceinline__ void mma16816(float* c, const unsigned* a,
                                                const unsigned* b) {
    asm volatile(
        "mma.sync.aligned.m16n8k16.row.col.f32.f16.f16.f32 "
        "{%0,%1,%2,%3}, {%4,%5,%6,%7}, {%8,%9}, {%0,%1,%2,%3};"
        : "+f"(c[0]), "+f"(c[1]), "+f"(c[2]), "+f"(c[3])
        : "r"(a[0]), "r"(a[1]), "r"(a[2]), "r"(a[3]), "r"(b[0]), "r"(b[1]));
}
static __device__ __forceinline__ float silu(float v) {
    return v / (1.0f + __expf(-v));
}

// smem strides (halves)
#define ASTR 40     // 128 x 32 A tile, padded: conflict-free ldmatrix
#define BSTR 136    // 32 x 128 B tile, padded

// ---------------------------------------------------------------------------
__device__ int classify_small(const unsigned* w) {
    bool i64 = true, i32 = true;
    for (int j = 0; j < 32; j++) {
        unsigned v = w[j];
        if (j & 1) { if (v != 0u) i64 = false; }
        else       { if (v >= 8u) i64 = false; }
        if (v >= 8u) i32 = false;
    }
    if (i64) return 1;
    if (i32) return 2;
    return 0;
}

__global__ void k_detect(const unsigned* smallA, const unsigned* smallB,
                         const float* bigA, const float* bigB) {
    __shared__ float sA[256], sB[256];
    int t = threadIdx.x;
    float a = 0.f, b = 0.f;
    for (int i = t; i < 4096; i += 256) { a += fabsf(bigA[i]); b += fabsf(bigB[i]); }
    sA[t] = a; sB[t] = b;
    __syncthreads();
    for (int s = 128; s > 0; s >>= 1) {
        if (t < s) { sA[t] += sA[t + s]; sB[t] += sB[t + s]; }
        __syncthreads();
    }
    if (t < NE) g_cnt[t] = 0;
    if (t == 0) {
        g_flags[2] = (sA[0] > sB[0]) ? 1 : 0;   // larger scale (H^-0.5) => w1
        int tA = classify_small(smallA);
        if (tA != 0) { g_flags[0] = 1; g_flags[1] = (tA == 1); }
        else {
            int tB = classify_small(smallB);
            g_flags[0] = 0; g_flags[1] = (tB == 1);
        }
    }
}

__global__ void k_route(const void* smallA, const void* smallB) {
    int b = blockIdx.x * blockDim.x + threadIdx.x;
    if (b >= BATCH) return;
    const void*  idxp = g_flags[0] ? smallA : smallB;
    const float* rw   = (const float*)(g_flags[0] ? smallB : smallA);
    int e0, e1;
    if (g_flags[1]) {
        e0 = (int)((const long long*)idxp)[b * 2 + 0];
        e1 = (int)((const long long*)idxp)[b * 2 + 1];
    } else {
        e0 = ((const int*)idxp)[b * 2 + 0];
        e1 = ((const int*)idxp)[b * 2 + 1];
    }
    float w0 = rw[b * 2 + 0];
    float w1 = rw[b * 2 + 1];
    if (e0 == e1) {
        int p = atomicAdd(&g_cnt[e0], 1);
        g_tok[e0][p] = b; g_wgt[e0][p] = w0 + w1;
    } else {
        int p = atomicAdd(&g_cnt[e0], 1);
        g_tok[e0][p] = b; g_wgt[e0][p] = w0;
        p = atomicAdd(&g_cnt[e1], 1);
        g_tok[e1][p] = b; g_wgt[e1][p] = w1;
    }
}

// ---------------------------------------------------------------------------
// GEMM1: H[e,pos,f] = silu(X[tok] . W1[e][:,f]); fp16 mma.sync, CTA 128x128xBK32
__global__ __launch_bounds__(256, 1)
void k_gemm1(const float* __restrict__ X,
             const float* __restrict__ bigA, const float* __restrict__ bigB) {
    const float* W1 = g_flags[2] ? bigA : bigB;
    int e    = blockIdx.z;
    int cnt  = g_cnt[e];
    int row0 = blockIdx.y * 128;
    if (row0 >= cnt) return;
    int col0 = blockIdx.x * 128;

    __shared__ __align__(16) __half As[128 * ASTR];
    __shared__ __align__(16) __half Bs[32 * BSTR];
    __shared__ int stok[128];

    int tid = threadIdx.x, lane = tid & 31, wid = tid >> 5;
    if (tid < 128) {
        int r = row0 + tid;
        stok[tid] = (r < cnt) ? g_tok[e][r] : 0;
    }
    __syncthreads();

    const float* W = W1 + (size_t)e * HID * FFN + col0;

    int am = tid >> 1, akh = (tid & 1) * 16;
    const float* Ap = X + (size_t)stok[am] * HID + akh;
    int bk = tid >> 3, bn = (tid & 7) * 16;
    const float* Bp = W + (size_t)bk * FFN + bn;

    uint32_t sbA = smem_u32(As), sbB = smem_u32(Bs);
    uint32_t sA = sbA + (am * ASTR + akh) * 2;
    uint32_t sB = sbB + (bk * BSTR + bn) * 2;

    int wm = wid & 3, wn = wid >> 2;
    int grp = lane >> 2, tid4 = lane & 3;
    uint32_t aB = sbA + (((wm * 32 + (lane & 15)) * ASTR) + ((lane >> 4) * 8)) * 2;
    uint32_t bB = sbB + ((((lane & 7) + ((lane >> 3) & 1) * 8) * BSTR) +
                         wn * 64 + (lane >> 4) * 8) * 2;

    float acc[2][8][4] = {};
    float4 a4[4], b4[4];
#pragma unroll
    for (int j = 0; j < 4; j++) {
        a4[j] = *(const float4*)(Ap + j * 4);
        b4[j] = *(const float4*)(Bp + j * 4);
    }

    const int NIT = HID / 32;
    for (int it = 0; it < NIT; it++) {
        st4(sA,      h2(a4[0].x, a4[0].y), h2(a4[0].z, a4[0].w),
                     h2(a4[1].x, a4[1].y), h2(a4[1].z, a4[1].w));
        st4(sA + 16, h2(a4[2].x, a4[2].y), h2(a4[2].z, a4[2].w),
                     h2(a4[3].x, a4[3].y), h2(a4[3].z, a4[3].w));
        st4(sB,      h2(b4[0].x, b4[0].y), h2(b4[0].z, b4[0].w),
                     h2(b4[1].x, b4[1].y), h2(b4[1].z, b4[1].w));
        st4(sB + 16, h2(b4[2].x, b4[2].y), h2(b4[2].z, b4[2].w),
                     h2(b4[3].x, b4[3].y), h2(b4[3].z, b4[3].w));
        __syncthreads();
        if (it + 1 < NIT) {
            int k0 = (it + 1) * 32;
#pragma unroll
            for (int j = 0; j < 4; j++) {
                a4[j] = *(const float4*)(Ap + k0 + j * 4);
                b4[j] = *(const float4*)(Bp + (size_t)k0 * FFN + j * 4);
            }
        }
#pragma unroll
        for (int kk = 0; kk < 2; kk++) {
            unsigned afr[2][4];
            ldsm_x4(afr[0], aB + kk * 32);
            ldsm_x4(afr[1], aB + 16 * ASTR * 2 + kk * 32);
            unsigned bfr[8][2];
#pragma unroll
            for (int j2 = 0; j2 < 4; j2++) {
                unsigned t[4];
                ldsm_x4_t(t, bB + kk * 16 * BSTR * 2 + j2 * 32);
                bfr[j2 * 2][0] = t[0]; bfr[j2 * 2][1] = t[1];
                bfr[j2 * 2 + 1][0] = t[2]; bfr[j2 * 2 + 1][1] = t[3];
            }
#pragma unroll
            for (int mt = 0; mt < 2; mt++)
#pragma unroll
                for (int j = 0; j < 8; j++)
                    mma16816(acc[mt][j], afr[mt], bfr[j]);
        }
        __syncthreads();
    }

    // epilogue: silu -> fp16 g_H
#pragma unroll
    for (int mt = 0; mt < 2; mt++) {
        int rb = row0 + wm * 32 + mt * 16 + grp;
#pragma unroll
        for (int j = 0; j < 8; j++) {
            int cg = col0 + wn * 64 + j * 8 + tid4 * 2;
            float* c = acc[mt][j];
            if (rb < cnt) {
                __half2* Hr = (__half2*)(g_H + ((size_t)e * BATCH + rb) * FFN + cg);
                *Hr = __floats2half2_rn(silu(c[0]), silu(c[1]));
            }
            if (rb + 8 < cnt) {
                __half2* Hr = (__half2*)(g_H + ((size_t)e * BATCH + rb + 8) * FFN + cg);
                *Hr = __floats2half2_rn(silu(c[2]), silu(c[3]));
            }
        }
    }
}

// ---------------------------------------------------------------------------
// GEMM2: out[tok] += wgt * (H[e,pos,:] . W2[e][:,h])
__global__ __launch_bounds__(256, 1)
void k_gemm2(const float* __restrict__ bigA, const float* __restrict__ bigB,
             float* __restrict__ out) {
    const float* W2 = g_flags[2] ? bigB : bigA;
    int e    = blockIdx.z;
    int cnt  = g_cnt[e];
    int row0 = blockIdx.y * 128;
    if (row0 >= cnt) return;
    int col0 = blockIdx.x * 128;

    __shared__ __align__(16) __half As[128 * ASTR];
    __shared__ __align__(16) __half Bs[32 * BSTR];
    __shared__ int   stok[128];
    __shared__ float swt[128];

    int tid = threadIdx.x, lane = tid & 31, wid = tid >> 5;
    if (tid < 128) {
        int r = row0 + tid;
        stok[tid] = (r < cnt) ? g_tok[e][r] : 0;
        swt[tid]  = (r < cnt) ? g_wgt[e][r] : 0.0f;
    }
    __syncthreads();

    const float* W = W2 + (size_t)e * FFN * HID + col0;

    int am = tid >> 1, akh = (tid & 1) * 16;
    const __half* Ap = g_H + ((size_t)e * BATCH + row0 + am) * FFN + akh;
    int bk = tid >> 3, bn = (tid & 7) * 16;
    const float* Bp = W + (size_t)bk * HID + bn;

    uint32_t sbA = smem_u32(As), sbB = smem_u32(Bs);
    uint32_t sA = sbA + (am * ASTR + akh) * 2;
    uint32_t sB = sbB + (bk * BSTR + bn) * 2;

    int wm = wid & 3, wn = wid >> 2;
    int grp = lane >> 2, tid4 = lane & 3;
    uint32_t aB = sbA + (((wm * 32 + (lane & 15)) * ASTR) + ((lane >> 4) * 8)) * 2;
    uint32_t bB = sbB + ((((lane & 7) + ((lane >> 3) & 1) * 8) * BSTR) +
                         wn * 64 + (lane >> 4) * 8) * 2;

    float acc[2][8][4] = {};
    uint4 ua[2];
    float4 b4[4];
    ua[0] = *(const uint4*)(Ap);
    ua[1] = *(const uint4*)(Ap + 8);
#pragma unroll
    for (int j = 0; j < 4; j++) b4[j] = *(const float4*)(Bp + j * 4);

    const int NIT = FFN / 32;
    for (int it = 0; it < NIT; it++) {
        st4(sA,      ua[0].x, ua[0].y, ua[0].z, ua[0].w);
        st4(sA + 16, ua[1].x, ua[1].y, ua[1].z, ua[1].w);
        st4(sB,      h2(b4[0].x, b4[0].y), h2(b4[0].z, b4[0].w),
                     h2(b4[1].x, b4[1].y), h2(b4[1].z, b4[1].w));
        st4(sB + 16, h2(b4[2].x, b4[2].y), h2(b4[2].z, b4[2].w),
                     h2(b4[3].x, b4[3].y), h2(b4[3].z, b4[3].w));
        __syncthreads();
        if (it + 1 < NIT) {
            int k0 = (it + 1) * 32;
            ua[0] = *(const uint4*)(Ap + k0);
            ua[1] = *(const uint4*)(Ap + k0 + 8);
#pragma unroll
            for (int j = 0; j < 4; j++)
                b4[j] = *(const float4*)(Bp + (size_t)k0 * HID + j * 4);
        }
#pragma unroll
        for (int kk = 0; kk < 2; kk++) {
            unsigned afr[2][4];
            ldsm_x4(afr[0], aB + kk * 32);
            ldsm_x4(afr[1], aB + 16 * ASTR * 2 + kk * 32);
            unsigned bfr[8][2];
#pragma unroll
            for (int j2 = 0; j2 < 4; j2++) {
                unsigned t[4];
                ldsm_x4_t(t, bB + kk * 16 * BSTR * 2 + j2 * 32);
                bfr[j2 * 2][0] = t[0]; bfr[j2 * 2][1] = t[1];
                bfr[j2 * 2 + 1][0] = t[2]; bfr[j2 * 2 + 1][1] = t[3];
            }
#pragma unroll
            for (int mt = 0; mt < 2; mt++)
#pragma unroll
                for (int j = 0; j < 8; j++)
                    mma16816(acc[mt][j], afr[mt], bfr[j]);
        }
        __syncthreads();
    }

    // epilogue: weighted atomic scatter
#pragma unroll
    for (int mt = 0; mt < 2; mt++) {
        int lr = wm * 32 + mt * 16 + grp;     // local row in [0,128)
#pragma unroll
        for (int j = 0; j < 8; j++) {
            int cg = col0 + wn * 64 + j * 8 + tid4 * 2;
            float* c = acc[mt][j];
            if (row0 + lr < cnt) {
                int   t = stok[lr];
                float w = swt[lr];
                atomicAdd(&out[(size_t)t * HID + cg],     w * c[0]);
                atomicAdd(&out[(size_t)t * HID + cg + 1], w * c[1]);
            }
            if (row0 + lr + 8 < cnt) {
                int   t = stok[lr + 8];
                float w = swt[lr + 8];
                atomicAdd(&out[(size_t)t * HID + cg],     w * c[2]);
                atomicAdd(&out[(size_t)t * HID + cg + 1], w * c[3]);
            }
        }
    }
}

// ---------------------------------------------------------------------------
extern "C" void kernel_launch(void* const* d_in, const int* in_sizes, int n_in,
                              void* d_out, int out_size) {
    const float* X = nullptr;
    const void*  smallbuf[2] = {nullptr, nullptr};
    const float* bigbuf[2]   = {nullptr, nullptr};
    int ns = 0, nb = 0;
    for (int i = 0; i < n_in; i++) {
        long long s = in_sizes[i];
        if (s == (long long)BATCH * HID)            X = (const float*)d_in[i];
        else if (s == (long long)BATCH * 2)         { if (ns < 2) smallbuf[ns++] = d_in[i]; }
        else if (s == (long long)NE * HID * FFN)    { if (nb < 2) bigbuf[nb++] = (const float*)d_in[i]; }
    }
    float* out = (float*)d_out;

    cudaMemsetAsync(out, 0, (size_t)out_size * sizeof(float));
    k_detect<<<1, 256>>>((const unsigned*)smallbuf[0], (const unsigned*)smallbuf[1],
                         bigbuf[0], bigbuf[1]);
    k_route<<<(BATCH + 255) / 256, 256>>>(smallbuf[0], smallbuf[1]);
    k_gemm1<<<dim3(FFN / 128, BATCH / 128, NE), 256>>>(X, bigbuf[0], bigbuf[1]);
    k_gemm2<<<dim3(HID / 128, BATCH / 128, NE), 256>>>(bigbuf[0], bigbuf[1], out);
}

// round 6
// speedup vs baseline: 4.6597x; 1.4843x over previous
#include <cuda_runtime.h>
#include <cuda_fp16.h>
#include <cstdint>

#define BATCH 2048
#define HID   1024
#define FFN   4096
#define NE    8

// ---- device scratch ----
__device__ int    g_cnt[NE];
__device__ int    g_tok[NE][BATCH];
__device__ float  g_wgt[NE][BATCH];
__device__ int    g_flags[4];
__device__ __half g_H[(size_t)NE * BATCH * FFN];    // 128 MiB fp16 intermediate
__device__ __half g_WA[(size_t)NE * HID * FFN];     // 64 MiB: fp16(bigA)
__device__ __half g_WB[(size_t)NE * HID * FFN];     // 64 MiB: fp16(bigB)
__device__ __half g_Xh[(size_t)BATCH * HID];        // 4 MiB: fp16(X)

// ---- helpers ----
static __device__ __forceinline__ uint32_t smem_u32(const void* p) {
    uint32_t a;
    asm("{ .reg .u64 t; cvta.to.shared.u64 t, %1; cvt.u32.u64 %0, t; }" : "=r"(a) : "l"(p));
    return a;
}
static __device__ __forceinline__ void cp16(uint32_t dst, const void* src) {
    asm volatile("cp.async.cg.shared.global [%0], [%1], 16;" :: "r"(dst), "l"(src));
}
static __device__ __forceinline__ void cp_commit() {
    asm volatile("cp.async.commit_group;" ::: "memory");
}
static __device__ __forceinline__ void cp_wait1() {
    asm volatile("cp.async.wait_group 1;" ::: "memory");
}
static __device__ __forceinline__ void ldsm_x4(unsigned* r, uint32_t addr) {
    asm volatile("ldmatrix.sync.aligned.m8n8.x4.shared.b16 {%0,%1,%2,%3}, [%4];"
                 : "=r"(r[0]), "=r"(r[1]), "=r"(r[2]), "=r"(r[3]) : "r"(addr));
}
static __device__ __forceinline__ void ldsm_x4_t(unsigned* r, uint32_t addr) {
    asm volatile("ldmatrix.sync.aligned.m8n8.x4.trans.shared.b16 {%0,%1,%2,%3}, [%4];"
                 : "=r"(r[0]), "=r"(r[1]), "=r"(r[2]), "=r"(r[3]) : "r"(addr));
}
static __device__ __forceinline__ void mma16816(float* c, const unsigned* a,
                                                const unsigned* b) {
    asm volatile(
        "mma.sync.aligned.m16n8k16.row.col.f32.f16.f16.f32 "
        "{%0,%1,%2,%3}, {%4,%5,%6,%7}, {%8,%9}, {%0,%1,%2,%3};"
        : "+f"(c[0]), "+f"(c[1]), "+f"(c[2]), "+f"(c[3])
        : "r"(a[0]), "r"(a[1]), "r"(a[2]), "r"(a[3]), "r"(b[0]), "r"(b[1]));
}
static __device__ __forceinline__ float silu(float v) {
    return v / (1.0f + __expf(-v));
}

// smem tile strides (halves) — padded, conflict-free for ldmatrix
#define ASTR 40     // 128 x 32 A tile
#define BSTR 136    // 32 x 128 B tile
#define ASZ  (128 * ASTR * 2)          // 10240 B
#define BSZ  (32 * BSTR * 2)           // 8704 B
#define STG  (ASZ + BSZ)               // 18944 B
#define NSTG 3
#define SMEM_BYTES (NSTG * STG)        // 56832 B (dynamic)

// ---------------------------------------------------------------------------
__device__ int classify_small(const unsigned* w) {
    bool i64 = true, i32 = true;
    for (int j = 0; j < 32; j++) {
        unsigned v = w[j];
        if (j & 1) { if (v != 0u) i64 = false; }
        else       { if (v >= 8u) i64 = false; }
        if (v >= 8u) i32 = false;
    }
    if (i64) return 1;
    if (i32) return 2;
    return 0;
}

__global__ void k_detect(const unsigned* smallA, const unsigned* smallB,
                         const float* bigA, const float* bigB) {
    __shared__ float sA[256], sB[256];
    int t = threadIdx.x;
    float a = 0.f, b = 0.f;
    for (int i = t; i < 4096; i += 256) { a += fabsf(bigA[i]); b += fabsf(bigB[i]); }
    sA[t] = a; sB[t] = b;
    __syncthreads();
    for (int s = 128; s > 0; s >>= 1) {
        if (t < s) { sA[t] += sA[t + s]; sB[t] += sB[t + s]; }
        __syncthreads();
    }
    if (t < NE) g_cnt[t] = 0;
    if (t == 0) {
        g_flags[2] = (sA[0] > sB[0]) ? 1 : 0;   // larger scale (H^-0.5) => w1
        int tA = classify_small(smallA);
        if (tA != 0) { g_flags[0] = 1; g_flags[1] = (tA == 1); }
        else {
            int tB = classify_small(smallB);
            g_flags[0] = 0; g_flags[1] = (tB == 1);
        }
    }
}

__global__ void k_route(const void* smallA, const void* smallB) {
    int b = blockIdx.x * blockDim.x + threadIdx.x;
    if (b >= BATCH) return;
    const void*  idxp = g_flags[0] ? smallA : smallB;
    const float* rw   = (const float*)(g_flags[0] ? smallB : smallA);
    int e0, e1;
    if (g_flags[1]) {
        e0 = (int)((const long long*)idxp)[b * 2 + 0];
        e1 = (int)((const long long*)idxp)[b * 2 + 1];
    } else {
        e0 = ((const int*)idxp)[b * 2 + 0];
        e1 = ((const int*)idxp)[b * 2 + 1];
    }
    float w0 = rw[b * 2 + 0];
    float w1 = rw[b * 2 + 1];
    if (e0 == e1) {
        int p = atomicAdd(&g_cnt[e0], 1);
        g_tok[e0][p] = b; g_wgt[e0][p] = w0 + w1;
    } else {
        int p = atomicAdd(&g_cnt[e0], 1);
        g_tok[e0][p] = b; g_wgt[e0][p] = w0;
        p = atomicAdd(&g_cnt[e1], 1);
        g_tok[e1][p] = b; g_wgt[e1][p] = w1;
    }
}

// fp32 -> fp16 grid-stride converter (8 elems / thread / iter)
__global__ void k_cvt(const float4* __restrict__ src, uint4* __restrict__ dst,
                      int n8) {
    int i = blockIdx.x * blockDim.x + threadIdx.x;
    int stride = gridDim.x * blockDim.x;
    for (; i < n8; i += stride) {
        float4 v0 = src[i * 2], v1 = src[i * 2 + 1];
        __half2 h0 = __floats2half2_rn(v0.x, v0.y);
        __half2 h1 = __floats2half2_rn(v0.z, v0.w);
        __half2 h2 = __floats2half2_rn(v1.x, v1.y);
        __half2 h3 = __floats2half2_rn(v1.z, v1.w);
        uint4 o;
        o.x = *(uint32_t*)&h0; o.y = *(uint32_t*)&h1;
        o.z = *(uint32_t*)&h2; o.w = *(uint32_t*)&h3;
        dst[i] = o;
    }
}

// ---------------------------------------------------------------------------
// GEMM1: H[e,pos,f] = silu(X[tok] . W1[e][:,f]); fp16 mma, cp.async 3-stage
__global__ __launch_bounds__(256, 1)
void k_gemm1() {
    const __half* W1 = g_flags[2] ? g_WA : g_WB;
    int e    = blockIdx.z;
    int cnt  = g_cnt[e];
    int row0 = blockIdx.y * 128;
    if (row0 >= cnt) return;
    int col0 = blockIdx.x * 128;

    extern __shared__ char dyn[];
    __shared__ int stok[128];

    int tid = threadIdx.x, lane = tid & 31, wid = tid >> 5;
    if (tid < 128) {
        int r = row0 + tid;
        stok[tid] = (r < cnt) ? g_tok[e][r] : 0;
    }
    __syncthreads();

    const __half* W = W1 + (size_t)e * HID * FFN + col0;
    uint32_t sb = smem_u32(dyn);

    // copy mapping
    int arow = tid >> 1, aoff = (tid & 1) * 16;              // A: 128 rows x 2x16h
    const __half* Asrc = g_Xh + (size_t)stok[arow] * HID + aoff;
    int brow = tid >> 3, bch = (tid & 7) * 8;                // B: 32 rows x 2x(8h x2)
    const __half* Bsrc = W + (size_t)brow * FFN + bch;

    uint32_t adst = (uint32_t)(arow * ASTR + aoff) * 2;
    uint32_t bdst = (uint32_t)(ASZ) + (uint32_t)(brow * BSTR + bch) * 2;

    // fragment addressing (identical to R5 proven kernel)
    int wm = wid & 3, wn = wid >> 2;
    int grp = lane >> 2, tid4 = lane & 3;
    uint32_t aoffB = (uint32_t)(((wm * 32 + (lane & 15)) * ASTR) + ((lane >> 4) * 8)) * 2;
    uint32_t boffB = (uint32_t)(ASZ) +
                     (uint32_t)((((lane & 7) + ((lane >> 3) & 1) * 8) * BSTR) +
                                wn * 64 + (lane >> 4) * 8) * 2;

    const int NIT = HID / 32;

    // prologue: stages 0,1
#pragma unroll
    for (int s = 0; s < 2; s++) {
        uint32_t st = sb + s * STG;
        int k0 = s * 32;
        cp16(st + adst, Asrc + k0);
        cp16(st + adst + 16, Asrc + k0 + 8);
        cp16(st + bdst, Bsrc + (size_t)k0 * FFN);
        cp16(st + bdst + 128, Bsrc + (size_t)k0 * FFN + 64);
        cp_commit();
    }

    float acc[2][8][4] = {};
    int stg = 0;
    for (int it = 0; it < NIT; it++) {
        cp_wait1();
        __syncthreads();
        if (it + 2 < NIT) {
            uint32_t st = sb + ((stg + 2) % NSTG) * STG;
            int k0 = (it + 2) * 32;
            cp16(st + adst, Asrc + k0);
            cp16(st + adst + 16, Asrc + k0 + 8);
            cp16(st + bdst, Bsrc + (size_t)k0 * FFN);
            cp16(st + bdst + 128, Bsrc + (size_t)k0 * FFN + 64);
        }
        cp_commit();

        uint32_t aB = sb + stg * STG + aoffB;
        uint32_t bB = sb + stg * STG + boffB;
#pragma unroll
        for (int kk = 0; kk < 2; kk++) {
            unsigned afr[2][4];
            ldsm_x4(afr[0], aB + kk * 32);
            ldsm_x4(afr[1], aB + 16 * ASTR * 2 + kk * 32);
            unsigned bfr[8][2];
#pragma unroll
            for (int j2 = 0; j2 < 4; j2++) {
                unsigned t[4];
                ldsm_x4_t(t, bB + kk * 16 * BSTR * 2 + j2 * 32);
                bfr[j2 * 2][0] = t[0]; bfr[j2 * 2][1] = t[1];
                bfr[j2 * 2 + 1][0] = t[2]; bfr[j2 * 2 + 1][1] = t[3];
            }
#pragma unroll
            for (int mt = 0; mt < 2; mt++)
#pragma unroll
                for (int j = 0; j < 8; j++)
                    mma16816(acc[mt][j], afr[mt], bfr[j]);
        }
        stg = (stg + 1) % NSTG;
    }

    // epilogue: silu -> fp16 g_H
#pragma unroll
    for (int mt = 0; mt < 2; mt++) {
        int rb = row0 + wm * 32 + mt * 16 + grp;
#pragma unroll
        for (int j = 0; j < 8; j++) {
            int cg = col0 + wn * 64 + j * 8 + tid4 * 2;
            float* c = acc[mt][j];
            if (rb < cnt) {
                __half2* Hr = (__half2*)(g_H + ((size_t)e * BATCH + rb) * FFN + cg);
                *Hr = __floats2half2_rn(silu(c[0]), silu(c[1]));
            }
            if (rb + 8 < cnt) {
                __half2* Hr = (__half2*)(g_H + ((size_t)e * BATCH + rb + 8) * FFN + cg);
                *Hr = __floats2half2_rn(silu(c[2]), silu(c[3]));
            }
        }
    }
}

// ---------------------------------------------------------------------------
// GEMM2: out[tok] += wgt * (H[e,pos,:] . W2[e][:,h]); cp.async 3-stage
__global__ __launch_bounds__(256, 1)
void k_gemm2(float* __restrict__ out) {
    const __half* W2 = g_flags[2] ? g_WB : g_WA;
    int e    = blockIdx.z;
    int cnt  = g_cnt[e];
    int row0 = blockIdx.y * 128;
    if (row0 >= cnt) return;
    int col0 = blockIdx.x * 128;

    extern __shared__ char dyn[];
    __shared__ int   stok[128];
    __shared__ float swt[128];

    int tid = threadIdx.x, lane = tid & 31, wid = tid >> 5;
    if (tid < 128) {
        int r = row0 + tid;
        stok[tid] = (r < cnt) ? g_tok[e][r] : 0;
        swt[tid]  = (r < cnt) ? g_wgt[e][r] : 0.0f;
    }
    __syncthreads();

    const __half* W = W2 + (size_t)e * HID * FFN + col0;
    uint32_t sb = smem_u32(dyn);

    int arow = tid >> 1, aoff = (tid & 1) * 16;
    const __half* Asrc = g_H + ((size_t)e * BATCH + row0 + arow) * FFN + aoff;
    int brow = tid >> 3, bch = (tid & 7) * 8;
    const __half* Bsrc = W + (size_t)brow * HID + bch;

    uint32_t adst = (uint32_t)(arow * ASTR + aoff) * 2;
    uint32_t bdst = (uint32_t)(ASZ) + (uint32_t)(brow * BSTR + bch) * 2;

    int wm = wid & 3, wn = wid >> 2;
    int grp = lane >> 2, tid4 = lane & 3;
    uint32_t aoffB = (uint32_t)(((wm * 32 + (lane & 15)) * ASTR) + ((lane >> 4) * 8)) * 2;
    uint32_t boffB = (uint32_t)(ASZ) +
                     (uint32_t)((((lane & 7) + ((lane >> 3) & 1) * 8) * BSTR) +
                                wn * 64 + (lane >> 4) * 8) * 2;

    const int NIT = FFN / 32;

#pragma unroll
    for (int s = 0; s < 2; s++) {
        uint32_t st = sb + s * STG;
        int k0 = s * 32;
        cp16(st + adst, Asrc + k0);
        cp16(st + adst + 16, Asrc + k0 + 8);
        cp16(st + bdst, Bsrc + (size_t)k0 * HID);
        cp16(st + bdst + 128, Bsrc + (size_t)k0 * HID + 64);
        cp_commit();
    }

    float acc[2][8][4] = {};
    int stg = 0;
    for (int it = 0; it < NIT; it++) {
        cp_wait1();
        __syncthreads();
        if (it + 2 < NIT) {
            uint32_t st = sb + ((stg + 2) % NSTG) * STG;
            int k0 = (it + 2) * 32;
            cp16(st + adst, Asrc + k0);
            cp16(st + adst + 16, Asrc + k0 + 8);
            cp16(st + bdst, Bsrc + (size_t)k0 * HID);
            cp16(st + bdst + 128, Bsrc + (size_t)k0 * HID + 64);
        }
        cp_commit();

        uint32_t aB = sb + stg * STG + aoffB;
        uint32_t bB = sb + stg * STG + boffB;
#pragma unroll
        for (int kk = 0; kk < 2; kk++) {
            unsigned afr[2][4];
            ldsm_x4(afr[0], aB + kk * 32);
            ldsm_x4(afr[1], aB + 16 * ASTR * 2 + kk * 32);
            unsigned bfr[8][2];
#pragma unroll
            for (int j2 = 0; j2 < 4; j2++) {
                unsigned t[4];
                ldsm_x4_t(t, bB + kk * 16 * BSTR * 2 + j2 * 32);
                bfr[j2 * 2][0] = t[0]; bfr[j2 * 2][1] = t[1];
                bfr[j2 * 2 + 1][0] = t[2]; bfr[j2 * 2 + 1][1] = t[3];
            }
#pragma unroll
            for (int mt = 0; mt < 2; mt++)
#pragma unroll
                for (int j = 0; j < 8; j++)
                    mma16816(acc[mt][j], afr[mt], bfr[j]);
        }
        stg = (stg + 1) % NSTG;
    }

    // epilogue: weighted atomic scatter
#pragma unroll
    for (int mt = 0; mt < 2; mt++) {
        int lr = wm * 32 + mt * 16 + grp;
#pragma unroll
        for (int j = 0; j < 8; j++) {
            int cg = col0 + wn * 64 + j * 8 + tid4 * 2;
            float* c = acc[mt][j];
            if (row0 + lr < cnt) {
                int   t = stok[lr];
                float w = swt[lr];
                atomicAdd(&out[(size_t)t * HID + cg],     w * c[0]);
                atomicAdd(&out[(size_t)t * HID + cg + 1], w * c[1]);
            }
            if (row0 + lr + 8 < cnt) {
                int   t = stok[lr + 8];
                float w = swt[lr + 8];
                atomicAdd(&out[(size_t)t * HID + cg],     w * c[2]);
                atomicAdd(&out[(size_t)t * HID + cg + 1], w * c[3]);
            }
        }
    }
}

// ---------------------------------------------------------------------------
extern "C" void kernel_launch(void* const* d_in, const int* in_sizes, int n_in,
                              void* d_out, int out_size) {
    const float* X = nullptr;
    const void*  smallbuf[2] = {nullptr, nullptr};
    const float* bigbuf[2]   = {nullptr, nullptr};
    int ns = 0, nb = 0;
    for (int i = 0; i < n_in; i++) {
        long long s = in_sizes[i];
        if (s == (long long)BATCH * HID)            X = (const float*)d_in[i];
        else if (s == (long long)BATCH * 2)         { if (ns < 2) smallbuf[ns++] = d_in[i]; }
        else if (s == (long long)NE * HID * FFN)    { if (nb < 2) bigbuf[nb++] = (const float*)d_in[i]; }
    }
    float* out = (float*)d_out;

    cudaFuncSetAttribute(k_gemm1, cudaFuncAttributeMaxDynamicSharedMemorySize, SMEM_BYTES);
    cudaFuncSetAttribute(k_gemm2, cudaFuncAttributeMaxDynamicSharedMemorySize, SMEM_BYTES);

    // resolve device scratch addresses for converters
    __half *dWA, *dWB, *dXh;
    cudaGetSymbolAddress((void**)&dWA, g_WA);
    cudaGetSymbolAddress((void**)&dWB, g_WB);
    cudaGetSymbolAddress((void**)&dXh, g_Xh);

    cudaMemsetAsync(out, 0, (size_t)out_size * sizeof(float));
    k_detect<<<1, 256>>>((const unsigned*)smallbuf[0], (const unsigned*)smallbuf[1],
                         bigbuf[0], bigbuf[1]);
    k_route<<<(BATCH + 255) / 256, 256>>>(smallbuf[0], smallbuf[1]);

    int n8w = NE * HID * FFN / 8;
    k_cvt<<<1184, 256>>>((const float4*)bigbuf[0], (uint4*)dWA, n8w);
    k_cvt<<<1184, 256>>>((const float4*)bigbuf[1], (uint4*)dWB, n8w);
    k_cvt<<<256, 256>>>((const float4*)X, (uint4*)dXh, BATCH * HID / 8);

    k_gemm1<<<dim3(FFN / 128, BATCH / 128, NE), 256, SMEM_BYTES>>>();
    k_gemm2<<<dim3(HID / 128, BATCH / 128, NE), 256, SMEM_BYTES>>>(out);
}

// round 7
// speedup vs baseline: 4.6697x; 1.0022x over previous
#include <cuda_runtime.h>
#include <cuda_fp16.h>
#include <cstdint>

#define BATCH 2048
#define HID   1024
#define FFN   4096
#define NE    8

// ---- device scratch ----
__device__ int    g_cnt[NE];
__device__ int    g_tok[NE][BATCH];
__device__ float  g_wgt[NE][BATCH];
__device__ int    g_flags[4];
__device__ __half g_H[(size_t)NE * BATCH * FFN];    // 128 MiB fp16 intermediate
__device__ __half g_WA[(size_t)NE * HID * FFN];     // 64 MiB: fp16(bigA)
__device__ __half g_WB[(size_t)NE * HID * FFN];     // 64 MiB: fp16(bigB)
__device__ __half g_Xh[(size_t)BATCH * HID];        // 4 MiB: fp16(X)

// ---- helpers ----
static __device__ __forceinline__ uint32_t smem_u32(const void* p) {
    uint32_t a;
    asm("{ .reg .u64 t; cvta.to.shared.u64 t, %1; cvt.u32.u64 %0, t; }" : "=r"(a) : "l"(p));
    return a;
}
static __device__ __forceinline__ void cp16(uint32_t dst, const void* src) {
    asm volatile("cp.async.cg.shared.global [%0], [%1], 16;" :: "r"(dst), "l"(src));
}
static __device__ __forceinline__ void cp_commit() {
    asm volatile("cp.async.commit_group;" ::: "memory");
}
static __device__ __forceinline__ void cp_wait1() {
    asm volatile("cp.async.wait_group 1;" ::: "memory");
}
static __device__ __forceinline__ void ldsm_x4(unsigned* r, uint32_t addr) {
    asm volatile("ldmatrix.sync.aligned.m8n8.x4.shared.b16 {%0,%1,%2,%3}, [%4];"
                 : "=r"(r[0]), "=r"(r[1]), "=r"(r[2]), "=r"(r[3]) : "r"(addr));
}
static __device__ __forceinline__ void ldsm_x4_t(unsigned* r, uint32_t addr) {
    asm volatile("ldmatrix.sync.aligned.m8n8.x4.trans.shared.b16 {%0,%1,%2,%3}, [%4];"
                 : "=r"(r[0]), "=r"(r[1]), "=r"(r[2]), "=r"(r[3]) : "r"(addr));
}
static __device__ __forceinline__ void mma16816(float* c, const unsigned* a,
                                                const unsigned* b) {
    asm volatile(
        "mma.sync.aligned.m16n8k16.row.col.f32.f16.f16.f32 "
        "{%0,%1,%2,%3}, {%4,%5,%6,%7}, {%8,%9}, {%0,%1,%2,%3};"
        : "+f"(c[0]), "+f"(c[1]), "+f"(c[2]), "+f"(c[3])
        : "r"(a[0]), "r"(a[1]), "r"(a[2]), "r"(a[3]), "r"(b[0]), "r"(b[1]));
}
static __device__ __forceinline__ float silu(float v) {
    return v / (1.0f + __expf(-v));
}

// smem tile strides (halves) — padded, conflict-free for ldmatrix
#define ASTR 40     // 128 x 32 A tile
#define BSTR 136    // 32 x 128 B tile
#define ASZ  (128 * ASTR * 2)          // 10240 B
#define BSZ  (32 * BSTR * 2)           // 8704 B
#define STG  (ASZ + BSZ)               // 18944 B
#define NSTG 3
#define SMEM_BYTES (NSTG * STG)        // 56832 B (dynamic)

// ---------------------------------------------------------------------------
__device__ int classify_small(const unsigned* w) {
    bool i64 = true, i32 = true;
    for (int j = 0; j < 32; j++) {
        unsigned v = w[j];
        if (j & 1) { if (v != 0u) i64 = false; }
        else       { if (v >= 8u) i64 = false; }
        if (v >= 8u) i32 = false;
    }
    if (i64) return 1;
    if (i32) return 2;
    return 0;
}

__global__ void k_detect(const unsigned* smallA, const unsigned* smallB,
                         const float* bigA, const float* bigB) {
    __shared__ float sA[256], sB[256];
    int t = threadIdx.x;
    float a = 0.f, b = 0.f;
    for (int i = t; i < 4096; i += 256) { a += fabsf(bigA[i]); b += fabsf(bigB[i]); }
    sA[t] = a; sB[t] = b;
    __syncthreads();
    for (int s = 128; s > 0; s >>= 1) {
        if (t < s) { sA[t] += sA[t + s]; sB[t] += sB[t + s]; }
        __syncthreads();
    }
    if (t < NE) g_cnt[t] = 0;
    if (t == 0) {
        g_flags[2] = (sA[0] > sB[0]) ? 1 : 0;   // larger scale (H^-0.5) => w1
        int tA = classify_small(smallA);
        if (tA != 0) { g_flags[0] = 1; g_flags[1] = (tA == 1); }
        else {
            int tB = classify_small(smallB);
            g_flags[0] = 0; g_flags[1] = (tB == 1);
        }
    }
}

__global__ void k_route(const void* smallA, const void* smallB) {
    int b = blockIdx.x * blockDim.x + threadIdx.x;
    if (b >= BATCH) return;
    const void*  idxp = g_flags[0] ? smallA : smallB;
    const float* rw   = (const float*)(g_flags[0] ? smallB : smallA);
    int e0, e1;
    if (g_flags[1]) {
        e0 = (int)((const long long*)idxp)[b * 2 + 0];
        e1 = (int)((const long long*)idxp)[b * 2 + 1];
    } else {
        e0 = ((const int*)idxp)[b * 2 + 0];
        e1 = ((const int*)idxp)[b * 2 + 1];
    }
    float w0 = rw[b * 2 + 0];
    float w1 = rw[b * 2 + 1];
    if (e0 == e1) {
        int p = atomicAdd(&g_cnt[e0], 1);
        g_tok[e0][p] = b; g_wgt[e0][p] = w0 + w1;
    } else {
        int p = atomicAdd(&g_cnt[e0], 1);
        g_tok[e0][p] = b; g_wgt[e0][p] = w0;
        p = atomicAdd(&g_cnt[e1], 1);
        g_tok[e1][p] = b; g_wgt[e1][p] = w1;
    }
}

// fp32 -> fp16 grid-stride converter (8 elems / thread / iter)
__global__ void k_cvt(const float4* __restrict__ src, uint4* __restrict__ dst,
                      int n8) {
    int i = blockIdx.x * blockDim.x + threadIdx.x;
    int stride = gridDim.x * blockDim.x;
    for (; i < n8; i += stride) {
        float4 v0 = src[i * 2], v1 = src[i * 2 + 1];
        __half2 h0 = __floats2half2_rn(v0.x, v0.y);
        __half2 h1 = __floats2half2_rn(v0.z, v0.w);
        __half2 h2 = __floats2half2_rn(v1.x, v1.y);
        __half2 h3 = __floats2half2_rn(v1.z, v1.w);
        uint4 o;
        o.x = *(uint32_t*)&h0; o.y = *(uint32_t*)&h1;
        o.z = *(uint32_t*)&h2; o.w = *(uint32_t*)&h3;
        dst[i] = o;
    }
}

// ---------------------------------------------------------------------------
// GEMM1: H[e,pos,f] = silu(X[tok] . W1[e][:,f]); fp16 mma, cp.async 3-stage
__global__ __launch_bounds__(256, 1)
void k_gemm1() {
    const __half* W1 = g_flags[2] ? g_WA : g_WB;
    int e    = blockIdx.z;
    int cnt  = g_cnt[e];
    int row0 = blockIdx.y * 128;
    if (row0 >= cnt) return;
    int col0 = blockIdx.x * 128;

    extern __shared__ char dyn[];
    __shared__ int stok[128];

    int tid = threadIdx.x, lane = tid & 31, wid = tid >> 5;
    if (tid < 128) {
        int r = row0 + tid;
        stok[tid] = (r < cnt) ? g_tok[e][r] : 0;
    }
    __syncthreads();

    const __half* W = W1 + (size_t)e * HID * FFN + col0;
    uint32_t sb = smem_u32(dyn);

    // copy mapping
    int arow = tid >> 1, aoff = (tid & 1) * 16;              // A: 128 rows x 2x16h
    const __half* Asrc = g_Xh + (size_t)stok[arow] * HID + aoff;
    int brow = tid >> 3, bch = (tid & 7) * 8;                // B: 32 rows x 2x(8h x2)
    const __half* Bsrc = W + (size_t)brow * FFN + bch;

    uint32_t adst = (uint32_t)(arow * ASTR + aoff) * 2;
    uint32_t bdst = (uint32_t)(ASZ) + (uint32_t)(brow * BSTR + bch) * 2;

    // fragment addressing (identical to R5 proven kernel)
    int wm = wid & 3, wn = wid >> 2;
    int grp = lane >> 2, tid4 = lane & 3;
    uint32_t aoffB = (uint32_t)(((wm * 32 + (lane & 15)) * ASTR) + ((lane >> 4) * 8)) * 2;
    uint32_t boffB = (uint32_t)(ASZ) +
                     (uint32_t)((((lane & 7) + ((lane >> 3) & 1) * 8) * BSTR) +
                                wn * 64 + (lane >> 4) * 8) * 2;

    const int NIT = HID / 32;

    // prologue: stages 0,1
#pragma unroll
    for (int s = 0; s < 2; s++) {
        uint32_t st = sb + s * STG;
        int k0 = s * 32;
        cp16(st + adst, Asrc + k0);
        cp16(st + adst + 16, Asrc + k0 + 8);
        cp16(st + bdst, Bsrc + (size_t)k0 * FFN);
        cp16(st + bdst + 128, Bsrc + (size_t)k0 * FFN + 64);
        cp_commit();
    }

    float acc[2][8][4] = {};
    int stg = 0;
    for (int it = 0; it < NIT; it++) {
        cp_wait1();
        __syncthreads();
        if (it + 2 < NIT) {
            uint32_t st = sb + ((stg + 2) % NSTG) * STG;
            int k0 = (it + 2) * 32;
            cp16(st + adst, Asrc + k0);
            cp16(st + adst + 16, Asrc + k0 + 8);
            cp16(st + bdst, Bsrc + (size_t)k0 * FFN);
            cp16(st + bdst + 128, Bsrc + (size_t)k0 * FFN + 64);
        }
        cp_commit();

        uint32_t aB = sb + stg * STG + aoffB;
        uint32_t bB = sb + stg * STG + boffB;
#pragma unroll
        for (int kk = 0; kk < 2; kk++) {
            unsigned afr[2][4];
            ldsm_x4(afr[0], aB + kk * 32);
            ldsm_x4(afr[1], aB + 16 * ASTR * 2 + kk * 32);
            unsigned bfr[8][2];
#pragma unroll
            for (int j2 = 0; j2 < 4; j2++) {
                unsigned t[4];
                ldsm_x4_t(t, bB + kk * 16 * BSTR * 2 + j2 * 32);
                bfr[j2 * 2][0] = t[0]; bfr[j2 * 2][1] = t[1];
                bfr[j2 * 2 + 1][0] = t[2]; bfr[j2 * 2 + 1][1] = t[3];
            }
#pragma unroll
            for (int mt = 0; mt < 2; mt++)
#pragma unroll
                for (int j = 0; j < 8; j++)
                    mma16816(acc[mt][j], afr[mt], bfr[j]);
        }
        stg = (stg + 1) % NSTG;
    }

    // epilogue: silu -> fp16 g_H
#pragma unroll
    for (int mt = 0; mt < 2; mt++) {
        int rb = row0 + wm * 32 + mt * 16 + grp;
#pragma unroll
        for (int j = 0; j < 8; j++) {
            int cg = col0 + wn * 64 + j * 8 + tid4 * 2;
            float* c = acc[mt][j];
            if (rb < cnt) {
                __half2* Hr = (__half2*)(g_H + ((size_t)e * BATCH + rb) * FFN + cg);
                *Hr = __floats2half2_rn(silu(c[0]), silu(c[1]));
            }
            if (rb + 8 < cnt) {
                __half2* Hr = (__half2*)(g_H + ((size_t)e * BATCH + rb + 8) * FFN + cg);
                *Hr = __floats2half2_rn(silu(c[2]), silu(c[3]));
            }
        }
    }
}

// ---------------------------------------------------------------------------
// GEMM2: out[tok] += wgt * (H[e,pos,:] . W2[e][:,h]); cp.async 3-stage
__global__ __launch_bounds__(256, 1)
void k_gemm2(float* __restrict__ out) {
    const __half* W2 = g_flags[2] ? g_WB : g_WA;
    int e    = blockIdx.z;
    int cnt  = g_cnt[e];
    int row0 = blockIdx.y * 128;
    if (row0 >= cnt) return;
    int col0 = blockIdx.x * 128;

    extern __shared__ char dyn[];
    __shared__ int   stok[128];
    __shared__ float swt[128];

    int tid = threadIdx.x, lane = tid & 31, wid = tid >> 5;
    if (tid < 128) {
        int r = row0 + tid;
        stok[tid] = (r < cnt) ? g_tok[e][r] : 0;
        swt[tid]  = (r < cnt) ? g_wgt[e][r] : 0.0f;
    }
    __syncthreads();

    const __half* W = W2 + (size_t)e * HID * FFN + col0;
    uint32_t sb = smem_u32(dyn);

    int arow = tid >> 1, aoff = (tid & 1) * 16;
    const __half* Asrc = g_H + ((size_t)e * BATCH + row0 + arow) * FFN + aoff;
    int brow = tid >> 3, bch = (tid & 7) * 8;
    const __half* Bsrc = W + (size_t)brow * HID + bch;

    uint32_t adst = (uint32_t)(arow * ASTR + aoff) * 2;
    uint32_t bdst = (uint32_t)(ASZ) + (uint32_t)(brow * BSTR + bch) * 2;

    int wm = wid & 3, wn = wid >> 2;
    int grp = lane >> 2, tid4 = lane & 3;
    uint32_t aoffB = (uint32_t)(((wm * 32 + (lane & 15)) * ASTR) + ((lane >> 4) * 8)) * 2;
    uint32_t boffB = (uint32_t)(ASZ) +
                     (uint32_t)((((lane & 7) + ((lane >> 3) & 1) * 8) * BSTR) +
                                wn * 64 + (lane >> 4) * 8) * 2;

    const int NIT = FFN / 32;

#pragma unroll
    for (int s = 0; s < 2; s++) {
        uint32_t st = sb + s * STG;
        int k0 = s * 32;
        cp16(st + adst, Asrc + k0);
        cp16(st + adst + 16, Asrc + k0 + 8);
        cp16(st + bdst, Bsrc + (size_t)k0 * HID);
        cp16(st + bdst + 128, Bsrc + (size_t)k0 * HID + 64);
        cp_commit();
    }

    float acc[2][8][4] = {};
    int stg = 0;
    for (int it = 0; it < NIT; it++) {
        cp_wait1();
        __syncthreads();
        if (it + 2 < NIT) {
            uint32_t st = sb + ((stg + 2) % NSTG) * STG;
            int k0 = (it + 2) * 32;
            cp16(st + adst, Asrc + k0);
            cp16(st + adst + 16, Asrc + k0 + 8);
            cp16(st + bdst, Bsrc + (size_t)k0 * HID);
            cp16(st + bdst + 128, Bsrc + (size_t)k0 * HID + 64);
        }
        cp_commit();

        uint32_t aB = sb + stg * STG + aoffB;
        uint32_t bB = sb + stg * STG + boffB;
#pragma unroll
        for (int kk = 0; kk < 2; kk++) {
            unsigned afr[2][4];
            ldsm_x4(afr[0], aB + kk * 32);
            ldsm_x4(afr[1], aB + 16 * ASTR * 2 + kk * 32);
            unsigned bfr[8][2];
#pragma unroll
            for (int j2 = 0; j2 < 4; j2++) {
                unsigned t[4];
                ldsm_x4_t(t, bB + kk * 16 * BSTR * 2 + j2 * 32);
                bfr[j2 * 2][0] = t[0]; bfr[j2 * 2][1] = t[1];
                bfr[j2 * 2 + 1][0] = t[2]; bfr[j2 * 2 + 1][1] = t[3];
            }
#pragma unroll
            for (int mt = 0; mt < 2; mt++)
#pragma unroll
                for (int j = 0; j < 8; j++)
                    mma16816(acc[mt][j], afr[mt], bfr[j]);
        }
        stg = (stg + 1) % NSTG;
    }

    // epilogue: weighted atomic scatter
#pragma unroll
    for (int mt = 0; mt < 2; mt++) {
        int lr = wm * 32 + mt * 16 + grp;
#pragma unroll
        for (int j = 0; j < 8; j++) {
            int cg = col0 + wn * 64 + j * 8 + tid4 * 2;
            float* c = acc[mt][j];
            if (row0 + lr < cnt) {
                int   t = stok[lr];
                float w = swt[lr];
                atomicAdd(&out[(size_t)t * HID + cg],     w * c[0]);
                atomicAdd(&out[(size_t)t * HID + cg + 1], w * c[1]);
            }
            if (row0 + lr + 8 < cnt) {
                int   t = stok[lr + 8];
                float w = swt[lr + 8];
                atomicAdd(&out[(size_t)t * HID + cg],     w * c[2]);
                atomicAdd(&out[(size_t)t * HID + cg + 1], w * c[3]);
            }
        }
    }
}

// ---------------------------------------------------------------------------
extern "C" void kernel_launch(void* const* d_in, const int* in_sizes, int n_in,
                              void* d_out, int out_size) {
    const float* X = nullptr;
    const void*  smallbuf[2] = {nullptr, nullptr};
    const float* bigbuf[2]   = {nullptr, nullptr};
    int ns = 0, nb = 0;
    for (int i = 0; i < n_in; i++) {
        long long s = in_sizes[i];
        if (s == (long long)BATCH * HID)            X = (const float*)d_in[i];
        else if (s == (long long)BATCH * 2)         { if (ns < 2) smallbuf[ns++] = d_in[i]; }
        else if (s == (long long)NE * HID * FFN)    { if (nb < 2) bigbuf[nb++] = (const float*)d_in[i]; }
    }
    float* out = (float*)d_out;

    cudaFuncSetAttribute(k_gemm1, cudaFuncAttributeMaxDynamicSharedMemorySize, SMEM_BYTES);
    cudaFuncSetAttribute(k_gemm2, cudaFuncAttributeMaxDynamicSharedMemorySize, SMEM_BYTES);

    // resolve device scratch addresses for converters
    __half *dWA, *dWB, *dXh;
    cudaGetSymbolAddress((void**)&dWA, g_WA);
    cudaGetSymbolAddress((void**)&dWB, g_WB);
    cudaGetSymbolAddress((void**)&dXh, g_Xh);

    cudaMemsetAsync(out, 0, (size_t)out_size * sizeof(float));
    k_detect<<<1, 256>>>((const unsigned*)smallbuf[0], (const unsigned*)smallbuf[1],
                         bigbuf[0], bigbuf[1]);
    k_route<<<(BATCH + 255) / 256, 256>>>(smallbuf[0], smallbuf[1]);

    int n8w = NE * HID * FFN / 8;
    k_cvt<<<1184, 256>>>((const float4*)bigbuf[0], (uint4*)dWA, n8w);
    k_cvt<<<1184, 256>>>((const float4*)bigbuf[1], (uint4*)dWB, n8w);
    k_cvt<<<256, 256>>>((const float4*)X, (uint4*)dXh, BATCH * HID / 8);

    k_gemm1<<<dim3(FFN / 128, BATCH / 128, NE), 256, SMEM_BYTES>>>();
    k_gemm2<<<dim3(HID / 128, BATCH / 128, NE), 256, SMEM_BYTES>>>(out);
}